// round 3
// baseline (speedup 1.0000x reference)
#include <cuda_runtime.h>
#include <cstdint>

// Problem constants
#define NUM_E   1024
#define DIM     128
#define HW      4096          // 64*64
#define N_TOTAL 65536         // 16*4096 rows (each a 128-dim vector)
#define NBLOCKS 512           // N_TOTAL / 128

// Output layout (flattened tuple, float32):
//   [0, 8388608)            z_q_st  in (b, c, h, w) order
//   [8388608]               loss            = 1.25 * S
//   [8388609, 8454145)      encoding_indices (as float)
//   [8454145]               commitment_loss = 0.25 * S
//   [8454146]               codebook_loss   = S
#define OFF_LOSS   8388608
#define OFF_IDX    8388609
#define OFF_COMMIT 8454145
#define OFF_CODE   8454146

__device__ float d_enorm[NUM_E];
__device__ float d_blockS[NBLOCKS];

// ---------------------------------------------------------------------------
// Kernel 0: per-code squared norms ||e_k||^2 (fp32, squares rounded then sum;
// any order is fine — tolerance analysis shows ~1e-11 slack is harmless)
// ---------------------------------------------------------------------------
__global__ void enorm_kernel(const float* __restrict__ emb) {
    int k    = blockIdx.x * 8 + (threadIdx.x >> 5);
    int lane = threadIdx.x & 31;
    const float4* row = (const float4*)(emb + (size_t)k * DIM);
    float4 v = row[lane];
    float s = __fadd_rn(__fadd_rn(__fmul_rn(v.x, v.x), __fmul_rn(v.y, v.y)),
                        __fadd_rn(__fmul_rn(v.z, v.z), __fmul_rn(v.w, v.w)));
    #pragma unroll
    for (int o = 16; o; o >>= 1) s = __fadd_rn(s, __shfl_xor_sync(0xffffffffu, s, o));
    if (lane == 0) d_enorm[k] = s;
}

// ---------------------------------------------------------------------------
// Main kernel: fused distance-GEMM + argmin + gather + partial loss
// 512 blocks x 256 threads. Block tile: 128 n x 1024 k (8 k-tiles of 128).
// ---------------------------------------------------------------------------
// Dynamic SMEM partition (float offsets):
//   zsm   [128][128]  : 16384  (z tile, [d][n])
//   esm   [16][128]   :  2048  (embedding d-chunk, [d][k])
//   candv [128][16]   :  2048
//   candk [128][16]   :  2048  (ints)
//   idxsm [128]       :   128  (ints)
//   wsum  [8]         :     8
//   z2sm  [128]       :   128  (sequential-order fp32 ||z_n||^2)
#define SM_ZSM   0
#define SM_ESM   16384
#define SM_CANDV 18432
#define SM_CANDK 20480
#define SM_IDX   22528
#define SM_WSUM  22656
#define SM_Z2    22664
#define SMEM_FLOATS 22792
#define SMEM_BYTES  (SMEM_FLOATS * 4)

__global__ __launch_bounds__(256, 2)
void vq_main_kernel(const float* __restrict__ z,
                    const float* __restrict__ emb,
                    float* __restrict__ out) {
    extern __shared__ float smem[];
    float (*zsm)[128]   = (float (*)[128])(smem + SM_ZSM);
    float (*esm)[128]   = (float (*)[128])(smem + SM_ESM);
    float (*candv)[16]  = (float (*)[16])(smem + SM_CANDV);
    int   (*candk)[16]  = (int   (*)[16])(smem + SM_CANDK);
    int   *idxsm        = (int*)(smem + SM_IDX);
    float *wsum         = smem + SM_WSUM;
    float *z2sm         = smem + SM_Z2;

    const int t   = threadIdx.x;
    const int blk = blockIdx.x;
    const int n0  = blk * 128;
    const int b   = n0 >> 12;       // n0 / 4096
    const int hw0 = n0 & 4095;
    const float* zbase = z + (size_t)b * (DIM * HW) + hw0;

    // ---- load z tile: zsm[d][n] = z[b][d][hw0 + n] (coalesced float4) ----
    {
        int n4 = (t & 31) * 4;
        #pragma unroll
        for (int i = 0; i < 16; i++) {
            int d = (t >> 5) + i * 8;
            float4 v = *(const float4*)(zbase + (size_t)d * HW + n4);
            *(float4*)(&zsm[d][n4]) = v;
        }
    }
    __syncthreads();

    // ---- z2[n]: STRICTLY SEQUENTIAL fp32 sum over c of fl(z_c^2),
    //      replicating jnp.sum(z_flat**2, axis=-1) (CPU sequential hypothesis)
    if (t < 128) {
        float acc = 0.f;
        #pragma unroll 1
        for (int d = 0; d < 128; d++) {
            float v = zsm[d][t];
            acc = __fadd_rn(acc, __fmul_rn(v, v));
        }
        z2sm[t] = acc;
    }
    __syncthreads();

    const int tx = t & 15;
    const int ty = t >> 4;

    float z2r[8];
    #pragma unroll
    for (int i = 0; i < 8; i++) z2r[i] = z2sm[ty * 8 + i];

    float bestv[8];
    int   bestk[8];
    #pragma unroll
    for (int i = 0; i < 8; i++) { bestv[i] = 3.4e38f; bestk[i] = 0; }

    for (int kt = 0; kt < 8; kt++) {
        float acc[8][8];
        #pragma unroll
        for (int i = 0; i < 8; i++)
            #pragma unroll
            for (int j = 0; j < 8; j++) acc[i][j] = 0.f;

        for (int dc = 0; dc < 8; dc++) {
            __syncthreads();
            // load e chunk (128 k x 16 d), transposed into esm[d][k]
            {
                int k     = t >> 1;
                int dbase = (t & 1) * 8;
                const float* erow = emb + (size_t)(kt * 128 + k) * DIM
                                        + dc * 16 + dbase;
                float4 a  = *(const float4*)(erow);
                float4 bb = *(const float4*)(erow + 4);
                esm[dbase + 0][k] = a.x;  esm[dbase + 1][k] = a.y;
                esm[dbase + 2][k] = a.z;  esm[dbase + 3][k] = a.w;
                esm[dbase + 4][k] = bb.x; esm[dbase + 5][k] = bb.y;
                esm[dbase + 6][k] = bb.z; esm[dbase + 7][k] = bb.w;
            }
            __syncthreads();

            const int dglob = dc * 16;
            #pragma unroll
            for (int dd = 0; dd < 16; dd++) {
                float4 z0 = *(const float4*)(&zsm[dglob + dd][ty * 8]);
                float4 z1 = *(const float4*)(&zsm[dglob + dd][ty * 8 + 4]);
                float4 e0 = *(const float4*)(&esm[dd][tx * 8]);
                float4 e1 = *(const float4*)(&esm[dd][tx * 8 + 4]);
                float zf[8] = {z0.x, z0.y, z0.z, z0.w, z1.x, z1.y, z1.z, z1.w};
                float ef[8] = {e0.x, e0.y, e0.z, e0.w, e1.x, e1.y, e1.z, e1.w};
                #pragma unroll
                for (int i = 0; i < 8; i++)
                    #pragma unroll
                    for (int j = 0; j < 8; j++)
                        acc[i][j] = fmaf(zf[i], ef[j], acc[i][j]);
            }
        }

        // score replicates reference fp32 ops exactly:
        //   a = fl32(z2 + e2_k); s = fl32(a - fl32(2*dot))
        // running argmin, k ascending => first (lowest-index) min kept
        #pragma unroll
        for (int j = 0; j < 8; j++) {
            int kk  = kt * 128 + tx * 8 + j;
            float en = d_enorm[kk];
            #pragma unroll
            for (int i = 0; i < 8; i++) {
                float a = __fadd_rn(z2r[i], en);
                float s = __fadd_rn(a, __fmul_rn(-2.0f, acc[i][j]));
                if (s < bestv[i]) { bestv[i] = s; bestk[i] = kk; }
            }
        }
    }

    // ---- cross-thread argmin reduction over the 16 tx candidates per n ----
    __syncthreads();
    #pragma unroll
    for (int i = 0; i < 8; i++) {
        candv[ty * 8 + i][tx] = bestv[i];
        candk[ty * 8 + i][tx] = bestk[i];
    }
    __syncthreads();
    if (t < 128) {
        float bv = candv[t][0];
        int   bk = candk[t][0];
        #pragma unroll
        for (int j = 1; j < 16; j++) {
            float v = candv[t][j];
            int   kk = candk[t][j];
            if (v < bv || (v == bv && kk < bk)) { bv = v; bk = kk; }
        }
        idxsm[t] = bk;
        out[OFF_IDX + n0 + t] = (float)bk;
    }
    __syncthreads();

    // ---- epilogue: z_q gather + write (coalesced over n), partial S ----
    float sloc = 0.f;
    #pragma unroll 4
    for (int r = 0; r < 64; r++) {
        int linear = t + (r << 8);
        int d = linear >> 7;
        int n = linear & 127;
        float v    = emb[(size_t)idxsm[n] * DIM + d];
        float diff = v - zsm[d][n];
        sloc = fmaf(diff, diff, sloc);
        out[(size_t)b * (DIM * HW) + (size_t)d * HW + hw0 + n] = v;
    }
    #pragma unroll
    for (int o = 16; o; o >>= 1) sloc += __shfl_xor_sync(0xffffffffu, sloc, o);
    if ((t & 31) == 0) wsum[t >> 5] = sloc;
    __syncthreads();
    if (t == 0) {
        float s = 0.f;
        #pragma unroll
        for (int i = 0; i < 8; i++) s += wsum[i];
        d_blockS[blk] = s;
    }
}

// ---------------------------------------------------------------------------
// Finalize: deterministic tree-reduce of block partials, write loss scalars.
// ---------------------------------------------------------------------------
__global__ void finalize_kernel(float* __restrict__ out) {
    __shared__ float sh[NBLOCKS];
    int t = threadIdx.x;
    sh[t] = d_blockS[t];
    __syncthreads();
    for (int s = NBLOCKS / 2; s > 0; s >>= 1) {
        if (t < s) sh[t] += sh[t + s];
        __syncthreads();
    }
    if (t == 0) {
        float S = sh[0];
        out[OFF_LOSS]   = 1.25f * S;
        out[OFF_COMMIT] = 0.25f * S;
        out[OFF_CODE]   = S;
    }
}

// ---------------------------------------------------------------------------
extern "C" void kernel_launch(void* const* d_in, const int* in_sizes, int n_in,
                              void* d_out, int out_size) {
    const float* z   = (const float*)d_in[0];   // (16, 128, 64, 64)
    const float* emb = (const float*)d_in[1];   // (1024, 128)
    float* out = (float*)d_out;

    cudaFuncSetAttribute(vq_main_kernel,
                         cudaFuncAttributeMaxDynamicSharedMemorySize,
                         SMEM_BYTES);

    enorm_kernel<<<128, 256>>>(emb);
    vq_main_kernel<<<NBLOCKS, 256, SMEM_BYTES>>>(z, emb, out);
    finalize_kernel<<<1, NBLOCKS>>>(out);
}